// round 1
// baseline (speedup 1.0000x reference)
#include <cuda_runtime.h>
#include <math.h>

#define BB 2
#define NN 512
#define DIN 512
#define DM 256
#define TI 4

// scratch (static device globals — no allocation)
__device__ float g_h[BB * NN * DM];       // h[b][n][d], tanh(x@Wx+bx)
__device__ float g_ut[BB * DM * NN];      // u transposed: ut[b][d][n] = (pos@Wp)[b][n][d]

__device__ __forceinline__ float tanh_fast(float x) {
    float y;
    asm("tanh.approx.f32 %0, %1;" : "=f"(y) : "f"(x));
    return y;
}

// ---------------------------------------------------------------------------
// Kernel A: h = tanh(x @ Wx + bx)  and  ut = (pos @ Wp)^T   (4 rows per block)
// grid = B*N/TI = 256 blocks, 256 threads (thread t owns output column d=t)
// ---------------------------------------------------------------------------
__global__ __launch_bounds__(256) void kA(const float* __restrict__ x,
                                          const float* __restrict__ pos,
                                          const float* __restrict__ Wx,
                                          const float* __restrict__ bx,
                                          const float* __restrict__ Wp) {
    __shared__ float s_x[DIN][TI];   // x tile transposed: s_x[k][r], 8KB
    const int t = threadIdx.x;
    const int row0 = blockIdx.x * TI;           // global row in [0, B*N)

    // cooperative coalesced load of the x tile (r slow, col fast)
    for (int e = t; e < DIN * TI; e += 256) {
        int r = e / DIN, c = e % DIN;
        s_x[c][r] = x[(row0 + r) * DIN + c];
    }
    __syncthreads();

    float bias = bx[t];
    float a0 = bias, a1 = bias, a2 = bias, a3 = bias;
#pragma unroll 8
    for (int k = 0; k < DIN; k++) {
        float wv = Wx[k * DM + t];                        // coalesced, L2-hot
        float4 xv = *(const float4*)&s_x[k][0];           // broadcast LDS.128
        a0 += xv.x * wv;
        a1 += xv.y * wv;
        a2 += xv.z * wv;
        a3 += xv.w * wv;
    }
    g_h[(row0 + 0) * DM + t] = tanhf(a0);
    g_h[(row0 + 1) * DM + t] = tanhf(a1);
    g_h[(row0 + 2) * DM + t] = tanhf(a2);
    g_h[(row0 + 3) * DM + t] = tanhf(a3);

    // u projection: u[n][d] = sum_{k<4} pos[n][k] * Wp[k][d], stored transposed
    const int b = row0 / NN;
    const int n0 = row0 % NN;
    float w0 = Wp[0 * DM + t], w1 = Wp[1 * DM + t];
    float w2 = Wp[2 * DM + t], w3 = Wp[3 * DM + t];
#pragma unroll
    for (int r = 0; r < TI; r++) {
        const float* p = pos + (row0 + r) * 4;
        float u = p[0] * w0 + p[1] * w1 + p[2] * w2 + p[3] * w3;
        g_ut[(b * DM + t) * NN + n0 + r] = u;
    }
}

// ---------------------------------------------------------------------------
// Kernel B: fused scores + masked softmax + output GEMM.
// One block = TI=4 query rows (b, i0..i0+3). 256 threads.
// Thread t owns j-columns {t, t+256} for the score phase (8 accumulators),
// then d-column t for the output phase.
// ---------------------------------------------------------------------------
__global__ __launch_bounds__(256) void kB(const int* __restrict__ mask,
                                          const float* __restrict__ bp,
                                          const float* __restrict__ w,
                                          float* __restrict__ out,
                                          float* __restrict__ attn_out) {
    __shared__ float s_ui[DM][TI];   // (u_i + bp) transposed, 4KB
    __shared__ float s_w[DM];        // 1KB
    __shared__ float s_attn[NN][TI]; // scores -> probs, 8KB (16B row stride)

    const int t = threadIdx.x;
    const int blk = blockIdx.x;
    const int b = blk / (NN / TI);
    const int i0 = (blk % (NN / TI)) * TI;
    const float* ut_b = g_ut + b * DM * NN;

    if (t < DM) s_w[t] = w[t];
    for (int e = t; e < DM * TI; e += 256) {
        int d = e / TI, r = e % TI;
        s_ui[d][r] = ut_b[d * NN + i0 + r] + bp[d];
    }
    __syncthreads();

    // ---- score phase: acc[r] for j=t, acc[4+r] for j=t+256 ----
    float acc[2 * TI];
#pragma unroll
    for (int q = 0; q < 2 * TI; q++) acc[q] = 0.f;

    float nu1 = ut_b[t];
    float nu2 = ut_b[t + 256];
#pragma unroll 2
    for (int d = 0; d < DM; d++) {
        float u1 = nu1, u2 = nu2;
        int dn = (d + 1 < DM) ? d + 1 : d;            // prefetch next row
        nu1 = ut_b[dn * NN + t];
        nu2 = ut_b[dn * NN + t + 256];
        float wv = s_w[d];
        float4 ui = *(const float4*)&s_ui[d][0];      // broadcast LDS.128
        acc[0] += wv * tanh_fast(ui.x - u1);
        acc[1] += wv * tanh_fast(ui.y - u1);
        acc[2] += wv * tanh_fast(ui.z - u1);
        acc[3] += wv * tanh_fast(ui.w - u1);
        acc[4] += wv * tanh_fast(ui.x - u2);
        acc[5] += wv * tanh_fast(ui.y - u2);
        acc[6] += wv * tanh_fast(ui.z - u2);
        acc[7] += wv * tanh_fast(ui.w - u2);
    }
#pragma unroll
    for (int r = 0; r < TI; r++) {
        s_attn[t][r]       = acc[r];
        s_attn[t + 256][r] = acc[4 + r];
    }
    __syncthreads();

    // ---- masked softmax: warp wid (<TI) handles row i0+wid ----
    const int wid = t >> 5, lane = t & 31;
    if (wid < TI) {
        const int i = i0 + wid;
        const int* mrow = mask + (b * NN + i) * NN;
        float mx = -INFINITY;
        for (int j = lane; j < NN; j += 32) {
            if (mrow[j]) mx = fmaxf(mx, s_attn[j][wid]);
        }
#pragma unroll
        for (int o = 16; o; o >>= 1) mx = fmaxf(mx, __shfl_xor_sync(0xffffffffu, mx, o));
        float sum = 0.f;
        for (int j = lane; j < NN; j += 32) {
            float e = 0.f;
            if (mrow[j]) e = __expf(s_attn[j][wid] - mx);
            s_attn[j][wid] = e;
            sum += e;
        }
#pragma unroll
        for (int o = 16; o; o >>= 1) sum += __shfl_xor_sync(0xffffffffu, sum, o);
        float inv = (sum > 0.f) ? 1.f / sum : 0.f;
        float* arow = attn_out + (b * NN + i) * NN;
        for (int j = lane; j < NN; j += 32) {
            float p = s_attn[j][wid] * inv;
            s_attn[j][wid] = p;
            arow[j] = p;
        }
    }
    __syncthreads();

    // ---- output phase: out[i0+r][t] = sum_j p[r][j] * h[j][t] ----
    float o0 = 0.f, o1 = 0.f, o2 = 0.f, o3 = 0.f;
    const float* hb = g_h + b * NN * DM;
#pragma unroll 4
    for (int j = 0; j < NN; j++) {
        float hv = hb[j * DM + t];                    // coalesced, L2-hot
        float4 p = *(const float4*)&s_attn[j][0];     // broadcast LDS.128
        o0 += p.x * hv;
        o1 += p.y * hv;
        o2 += p.z * hv;
        o3 += p.w * hv;
    }
    out[(b * NN + i0 + 0) * DM + t] = o0;
    out[(b * NN + i0 + 1) * DM + t] = o1;
    out[(b * NN + i0 + 2) * DM + t] = o2;
    out[(b * NN + i0 + 3) * DM + t] = o3;
}

// ---------------------------------------------------------------------------
extern "C" void kernel_launch(void* const* d_in, const int* in_sizes, int n_in,
                              void* d_out, int out_size) {
    const float* x    = (const float*)d_in[0];  // [2,512,512]
    const float* pos  = (const float*)d_in[1];  // [2,512,4]
    const int*   mask = (const int*)  d_in[2];  // [2,512,512]
    const float* Wx   = (const float*)d_in[3];  // [512,256]
    const float* bx   = (const float*)d_in[4];  // [256]
    const float* Wp   = (const float*)d_in[5];  // [4,256]
    const float* bp   = (const float*)d_in[6];  // [256]
    const float* w    = (const float*)d_in[7];  // [256]

    float* out      = (float*)d_out;            // [2,512,256]
    float* attn_out = out + BB * NN * DM;       // [2,512,512]

    kA<<<BB * NN / TI, 256>>>(x, pos, Wx, bx, Wp);
    kB<<<BB * NN / TI, 256>>>(mask, bp, w, out, attn_out);
}

// round 2
// speedup vs baseline: 1.0530x; 1.0530x over previous
#include <cuda_runtime.h>
#include <math.h>

#define BB 2
#define NN 512
#define DIN 512
#define DM 256
#define TI 4

// scratch (static device globals — no allocation)
__device__ float g_h[BB * NN * DM];       // h[b][n][d], tanh(x@Wx+bx)
__device__ float g_ut[BB * DM * NN];      // u transposed: ut[b][d][n] = (pos@Wp)[b][n][d]

__device__ __forceinline__ float tanh_fast(float x) {
    float y;
    asm("tanh.approx.f32 %0, %1;" : "=f"(y) : "f"(x));
    return y;
}

// ---------------------------------------------------------------------------
// Kernel A: h = tanh(x @ Wx + bx)  and  ut = (pos @ Wp)^T   (4 rows per block)
// grid = B*N/TI = 256 blocks, 256 threads (thread t owns output column d=t)
// ---------------------------------------------------------------------------
__global__ __launch_bounds__(256) void kA(const float* __restrict__ x,
                                          const float* __restrict__ pos,
                                          const float* __restrict__ Wx,
                                          const float* __restrict__ bx,
                                          const float* __restrict__ Wp) {
    __shared__ float s_x[DIN][TI];   // x tile transposed: s_x[k][r], 8KB
    const int t = threadIdx.x;
    const int row0 = blockIdx.x * TI;           // global row in [0, B*N)

    for (int e = t; e < DIN * TI; e += 256) {
        int r = e / DIN, c = e % DIN;
        s_x[c][r] = x[(row0 + r) * DIN + c];
    }
    __syncthreads();

    float bias = bx[t];
    float a0 = bias, a1 = bias, a2 = bias, a3 = bias;
#pragma unroll 8
    for (int k = 0; k < DIN; k++) {
        float wv = Wx[k * DM + t];                        // coalesced, L2-hot
        float4 xv = *(const float4*)&s_x[k][0];           // broadcast LDS.128
        a0 += xv.x * wv;
        a1 += xv.y * wv;
        a2 += xv.z * wv;
        a3 += xv.w * wv;
    }
    g_h[(row0 + 0) * DM + t] = tanhf(a0);
    g_h[(row0 + 1) * DM + t] = tanhf(a1);
    g_h[(row0 + 2) * DM + t] = tanhf(a2);
    g_h[(row0 + 3) * DM + t] = tanhf(a3);

    const int b = row0 / NN;
    const int n0 = row0 % NN;
    float w0 = Wp[0 * DM + t], w1 = Wp[1 * DM + t];
    float w2 = Wp[2 * DM + t], w3 = Wp[3 * DM + t];
#pragma unroll
    for (int r = 0; r < TI; r++) {
        const float* p = pos + (row0 + r) * 4;
        float u = p[0] * w0 + p[1] * w1 + p[2] * w2 + p[3] * w3;
        g_ut[(b * DM + t) * NN + n0 + r] = u;
    }
}

// ---------------------------------------------------------------------------
// Kernel B: fused scores + masked softmax + output GEMM.
// One block = TI=4 query rows. 512 threads (16 warps).
// Score phase: thread t owns j-column t (4 accumulators, 4-deep prefetch).
// Output phase: thread t owns (d = t&255, row pair = t>>8).
// ---------------------------------------------------------------------------
__global__ __launch_bounds__(512) void kB(const int* __restrict__ mask,
                                          const float* __restrict__ bp,
                                          const float* __restrict__ w,
                                          float* __restrict__ out,
                                          float* __restrict__ attn_out) {
    __shared__ float s_ui[DM][TI];   // (u_i + bp) transposed, 4KB
    __shared__ float s_w[DM];        // 1KB
    __shared__ float s_attn[NN][TI]; // scores -> probs, 8KB

    const int t = threadIdx.x;
    const int blk = blockIdx.x;
    const int b = blk / (NN / TI);
    const int i0 = (blk % (NN / TI)) * TI;
    const float* ut_b = g_ut + b * DM * NN;

    if (t < DM) s_w[t] = w[t];
    for (int e = t; e < DM * TI; e += 512) {
        int d = e / TI, r = e % TI;
        s_ui[d][r] = ut_b[d * NN + i0 + r] + bp[d];
    }
    __syncthreads();

    // ---- score phase: j = t, 4-deep prefetch over d ----
    float acc0 = 0.f, acc1 = 0.f, acc2 = 0.f, acc3 = 0.f;
    const float* up = ut_b + t;
    float ubuf[4];
#pragma unroll
    for (int p = 0; p < 4; p++) ubuf[p] = up[p * NN];

    for (int d0 = 0; d0 < DM; d0 += 4) {
        float ucur[4];
#pragma unroll
        for (int p = 0; p < 4; p++) ucur[p] = ubuf[p];
        if (d0 + 4 < DM) {
#pragma unroll
            for (int p = 0; p < 4; p++) ubuf[p] = up[(d0 + 4 + p) * NN];
        }
#pragma unroll
        for (int dd = 0; dd < 4; dd++) {
            float wv = s_w[d0 + dd];
            float4 ui = *(const float4*)&s_ui[d0 + dd][0];  // broadcast LDS.128
            float uj = ucur[dd];
            acc0 += wv * tanh_fast(ui.x - uj);
            acc1 += wv * tanh_fast(ui.y - uj);
            acc2 += wv * tanh_fast(ui.z - uj);
            acc3 += wv * tanh_fast(ui.w - uj);
        }
    }
    *(float4*)&s_attn[t][0] = make_float4(acc0, acc1, acc2, acc3);
    __syncthreads();

    // ---- masked softmax: warp wid (<TI) handles row i0+wid ----
    const int wid = t >> 5, lane = t & 31;
    if (wid < TI) {
        const int i = i0 + wid;
        const int* mrow = mask + (b * NN + i) * NN;
        float mx = -INFINITY;
        for (int j = lane; j < NN; j += 32) {
            if (mrow[j]) mx = fmaxf(mx, s_attn[j][wid]);
        }
#pragma unroll
        for (int o = 16; o; o >>= 1) mx = fmaxf(mx, __shfl_xor_sync(0xffffffffu, mx, o));
        float sum = 0.f;
        for (int j = lane; j < NN; j += 32) {
            float e = 0.f;
            if (mrow[j]) e = __expf(s_attn[j][wid] - mx);
            s_attn[j][wid] = e;
            sum += e;
        }
#pragma unroll
        for (int o = 16; o; o >>= 1) sum += __shfl_xor_sync(0xffffffffu, sum, o);
        float inv = (sum > 0.f) ? 1.f / sum : 0.f;
        float* arow = attn_out + (b * NN + i) * NN;
        for (int j = lane; j < NN; j += 32) {
            float p = s_attn[j][wid] * inv;
            s_attn[j][wid] = p;
            arow[j] = p;
        }
    }
    __syncthreads();

    // ---- output phase: thread t -> d = t&255, rows {2*half, 2*half+1} ----
    const int d = t & (DM - 1);
    const int half = t >> 8;                 // 0 or 1
    float o0 = 0.f, o1 = 0.f;
    const float* hb = g_h + b * NN * DM + d;
#pragma unroll 4
    for (int j = 0; j < NN; j++) {
        float hv = hb[j * DM];                          // coalesced, L1/L2-hot
        float2 p = *(const float2*)&s_attn[j][2 * half]; // broadcast LDS.64
        o0 += p.x * hv;
        o1 += p.y * hv;
    }
    out[(b * NN + i0 + 2 * half + 0) * DM + d] = o0;
    out[(b * NN + i0 + 2 * half + 1) * DM + d] = o1;
}

// ---------------------------------------------------------------------------
extern "C" void kernel_launch(void* const* d_in, const int* in_sizes, int n_in,
                              void* d_out, int out_size) {
    const float* x    = (const float*)d_in[0];  // [2,512,512]
    const float* pos  = (const float*)d_in[1];  // [2,512,4]
    const int*   mask = (const int*)  d_in[2];  // [2,512,512]
    const float* Wx   = (const float*)d_in[3];  // [512,256]
    const float* bx   = (const float*)d_in[4];  // [256]
    const float* Wp   = (const float*)d_in[5];  // [4,256]
    const float* bp   = (const float*)d_in[6];  // [256]
    const float* w    = (const float*)d_in[7];  // [256]

    float* out      = (float*)d_out;            // [2,512,256]
    float* attn_out = out + BB * NN * DM;       // [2,512,512]

    kA<<<BB * NN / TI, 256>>>(x, pos, Wx, bx, Wp);
    kB<<<BB * NN / TI, 512>>>(mask, bp, w, out, attn_out);
}

// round 3
// speedup vs baseline: 1.1724x; 1.1134x over previous
#include <cuda_runtime.h>
#include <math.h>

#define BB 2
#define NN 512
#define DIN 512
#define DM 256
#define TI 4
#define C2LOG2E 2.885390081777927f   // 2*log2(e)

// scratch (static device globals — no allocation)
__device__ float g_h[BB * NN * DM];    // h[b][n][d] = tanh(x@Wx+bx)
__device__ float g_pt[BB * DM * NN];   // P transposed: exp2(c*(u+bp))[b][d][n]
__device__ float g_qt[BB * DM * NN];   // Q transposed: exp2(-c*u)[b][d][n]

__device__ __forceinline__ float ex2_fast(float x) {
    float y; asm("ex2.approx.f32 %0, %1;" : "=f"(y) : "f"(x)); return y;
}
__device__ __forceinline__ float rcp_fast(float x) {
    float y; asm("rcp.approx.f32 %0, %1;" : "=f"(y) : "f"(x)); return y;
}

// ---------------------------------------------------------------------------
// Kernel A: h = tanh(x @ Wx + bx); P/Q = exp2(+-c*u) with u = pos @ Wp.
// grid = B*N/TI = 256 blocks, 256 threads (thread t owns column d=t)
// ---------------------------------------------------------------------------
__global__ __launch_bounds__(256) void kA(const float* __restrict__ x,
                                          const float* __restrict__ pos,
                                          const float* __restrict__ Wx,
                                          const float* __restrict__ bx,
                                          const float* __restrict__ Wp,
                                          const float* __restrict__ bp) {
    __shared__ float s_x[DIN][TI];   // x tile transposed, 8KB
    const int t = threadIdx.x;
    const int row0 = blockIdx.x * TI;

    for (int e = t; e < DIN * TI; e += 256) {
        int r = e / DIN, c = e % DIN;
        s_x[c][r] = x[(row0 + r) * DIN + c];
    }
    __syncthreads();

    float bias = bx[t];
    float a0 = bias, a1 = bias, a2 = bias, a3 = bias;
#pragma unroll 8
    for (int k = 0; k < DIN; k++) {
        float wv = Wx[k * DM + t];
        float4 xv = *(const float4*)&s_x[k][0];
        a0 += xv.x * wv;
        a1 += xv.y * wv;
        a2 += xv.z * wv;
        a3 += xv.w * wv;
    }
    g_h[(row0 + 0) * DM + t] = tanhf(a0);
    g_h[(row0 + 1) * DM + t] = tanhf(a1);
    g_h[(row0 + 2) * DM + t] = tanhf(a2);
    g_h[(row0 + 3) * DM + t] = tanhf(a3);

    const int b = row0 / NN;
    const int n0 = row0 % NN;
    const float w0 = Wp[0 * DM + t], w1 = Wp[1 * DM + t];
    const float w2 = Wp[2 * DM + t], w3 = Wp[3 * DM + t];
    const float bpv = bp[t];
#pragma unroll
    for (int r = 0; r < TI; r++) {
        const float* p = pos + (row0 + r) * 4;
        float u = p[0] * w0 + p[1] * w1 + p[2] * w2 + p[3] * w3;
        g_pt[(b * DM + t) * NN + n0 + r] = ex2_fast(C2LOG2E * (u + bpv));
        g_qt[(b * DM + t) * NN + n0 + r] = ex2_fast(-C2LOG2E * u);
    }
}

// ---------------------------------------------------------------------------
// Kernel B: fused scores (rational tanh via P*Q) + masked softmax + out GEMM.
// One block = TI=4 query rows, 512 threads.
// ---------------------------------------------------------------------------
__global__ __launch_bounds__(512) void kB(const int* __restrict__ mask,
                                          const float* __restrict__ w,
                                          float* __restrict__ out,
                                          float* __restrict__ attn_out) {
    __shared__ float s_pi[DM][TI];    // P_i rows, 4KB
    __shared__ float s_wn[DM];        // -2*w, 1KB
    __shared__ float s_attn[TI][NN];  // scores -> probs, row-contiguous, 8KB
    __shared__ float s_W;

    const int t = threadIdx.x;
    const int blk = blockIdx.x;
    const int b = blk / (NN / TI);
    const int i0 = (blk % (NN / TI)) * TI;
    const float* pt_b = g_pt + b * DM * NN;
    const float* qt_b = g_qt + b * DM * NN;

    if (t < DM) s_wn[t] = -2.0f * w[t];
    if (t < 32) {
        float s = 0.f;
#pragma unroll
        for (int k = 0; k < 8; k++) s += w[t + 32 * k];
#pragma unroll
        for (int o = 16; o; o >>= 1) s += __shfl_xor_sync(0xffffffffu, s, o);
        if (t == 0) s_W = s;
    }
    for (int e = t; e < DM * TI; e += 512) {
        int d = e >> 2, r = e & 3;
        s_pi[d][r] = pt_b[d * NN + i0 + r];
    }
    __syncthreads();
    const float W = s_W;

    // ---- score phase: thread owns j=t; batched reciprocals (1 RCP / 2 rows)
    float acc0 = 0.f, acc1 = 0.f, acc2 = 0.f, acc3 = 0.f;
    const float* qp = qt_b + t;
    float qbuf[4];
#pragma unroll
    for (int p = 0; p < 4; p++) qbuf[p] = qp[p * NN];

    for (int d0 = 0; d0 < DM; d0 += 4) {
        float qc[4];
#pragma unroll
        for (int p = 0; p < 4; p++) qc[p] = qbuf[p];
        if (d0 + 4 < DM) {
#pragma unroll
            for (int p = 0; p < 4; p++) qbuf[p] = qp[(d0 + 4 + p) * NN];
        }
#pragma unroll
        for (int dd = 0; dd < 4; dd++) {
            const int d = d0 + dd;
            const float wn = s_wn[d];
            const float4 pi = *(const float4*)&s_pi[d][0];  // broadcast LDS.128
            const float qj = qc[dd];
            float de0 = fmaf(pi.x, qj, 1.0f);
            float de1 = fmaf(pi.y, qj, 1.0f);
            float de2 = fmaf(pi.z, qj, 1.0f);
            float de3 = fmaf(pi.w, qj, 1.0f);
            float r01 = rcp_fast(de0 * de1);
            float r23 = rcp_fast(de2 * de3);
            float wr01 = wn * r01;
            float wr23 = wn * r23;
            acc0 += wr01 * de1;
            acc1 += wr01 * de0;
            acc2 += wr23 * de3;
            acc3 += wr23 * de2;
        }
    }
    s_attn[0][t] = W + acc0;
    s_attn[1][t] = W + acc1;
    s_attn[2][t] = W + acc2;
    s_attn[3][t] = W + acc3;
    __syncthreads();

    // ---- masked softmax: warp wid (<TI) handles row i0+wid, vectorized ----
    const int wid = t >> 5, lane = t & 31;
    if (wid < TI) {
        const int i = i0 + wid;
        const int4* m4 = (const int4*)(mask + (b * NN + i) * NN);
        float4* s4 = (float4*)&s_attn[wid][0];
        int4 mv[4];
        float4 sv[4];
#pragma unroll
        for (int k = 0; k < 4; k++) {
            mv[k] = m4[lane + 32 * k];
            sv[k] = s4[lane + 32 * k];
        }
        float mx = -INFINITY;
#pragma unroll
        for (int k = 0; k < 4; k++) {
            if (mv[k].x) mx = fmaxf(mx, sv[k].x);
            if (mv[k].y) mx = fmaxf(mx, sv[k].y);
            if (mv[k].z) mx = fmaxf(mx, sv[k].z);
            if (mv[k].w) mx = fmaxf(mx, sv[k].w);
        }
#pragma unroll
        for (int o = 16; o; o >>= 1) mx = fmaxf(mx, __shfl_xor_sync(0xffffffffu, mx, o));
        float sum = 0.f;
#pragma unroll
        for (int k = 0; k < 4; k++) {
            sv[k].x = mv[k].x ? __expf(sv[k].x - mx) : 0.f;
            sv[k].y = mv[k].y ? __expf(sv[k].y - mx) : 0.f;
            sv[k].z = mv[k].z ? __expf(sv[k].z - mx) : 0.f;
            sv[k].w = mv[k].w ? __expf(sv[k].w - mx) : 0.f;
            sum += sv[k].x + sv[k].y + sv[k].z + sv[k].w;
        }
#pragma unroll
        for (int o = 16; o; o >>= 1) sum += __shfl_xor_sync(0xffffffffu, sum, o);
        const float inv = (sum > 0.f) ? 1.f / sum : 0.f;
        float4* arow4 = (float4*)(attn_out + (b * NN + i) * NN);
#pragma unroll
        for (int k = 0; k < 4; k++) {
            sv[k].x *= inv; sv[k].y *= inv; sv[k].z *= inv; sv[k].w *= inv;
            s4[lane + 32 * k] = sv[k];
            arow4[lane + 32 * k] = sv[k];
        }
    }
    __syncthreads();

    // ---- output phase: thread t -> d = t&255, rows {2*half, 2*half+1} ----
    const int d = t & (DM - 1);
    const int half = t >> 8;
    float o0 = 0.f, o1 = 0.f;
    const float* hb = g_h + b * NN * DM + d;
    const float4* pA = (const float4*)&s_attn[2 * half][0];
    const float4* pB = (const float4*)&s_attn[2 * half + 1][0];
#pragma unroll 2
    for (int j4 = 0; j4 < NN / 4; j4++) {
        float4 a = pA[j4];  // broadcast LDS.128
        float4 c = pB[j4];
        float h0 = hb[(4 * j4 + 0) * DM];
        float h1 = hb[(4 * j4 + 1) * DM];
        float h2 = hb[(4 * j4 + 2) * DM];
        float h3 = hb[(4 * j4 + 3) * DM];
        o0 += a.x * h0; o0 += a.y * h1; o0 += a.z * h2; o0 += a.w * h3;
        o1 += c.x * h0; o1 += c.y * h1; o1 += c.z * h2; o1 += c.w * h3;
    }
    out[(b * NN + i0 + 2 * half + 0) * DM + d] = o0;
    out[(b * NN + i0 + 2 * half + 1) * DM + d] = o1;
}

// ---------------------------------------------------------------------------
extern "C" void kernel_launch(void* const* d_in, const int* in_sizes, int n_in,
                              void* d_out, int out_size) {
    const float* x    = (const float*)d_in[0];  // [2,512,512]
    const float* pos  = (const float*)d_in[1];  // [2,512,4]
    const int*   mask = (const int*)  d_in[2];  // [2,512,512]
    const float* Wx   = (const float*)d_in[3];  // [512,256]
    const float* bx   = (const float*)d_in[4];  // [256]
    const float* Wp   = (const float*)d_in[5];  // [4,256]
    const float* bp   = (const float*)d_in[6];  // [256]
    const float* w    = (const float*)d_in[7];  // [256]

    float* out      = (float*)d_out;            // [2,512,256]
    float* attn_out = out + BB * NN * DM;       // [2,512,512]

    kA<<<BB * NN / TI, 256>>>(x, pos, Wx, bx, Wp, bp);
    kB<<<BB * NN / TI, 512>>>(mask, w, out, attn_out);
}

// round 4
// speedup vs baseline: 1.1947x; 1.0191x over previous
#include <cuda_runtime.h>
#include <math.h>

#define BB 2
#define NN 512
#define DIN 512
#define DM 256
#define C2LOG2E 2.885390081777927f   // 2*log2(e)

// scratch (static device globals — no allocation)
__device__ float g_h[BB * NN * DM];    // h[b][n][d] = tanh(x@Wx+bx)
__device__ float g_p[BB * NN * DM];    // P row-major: exp2(c*(u+bp))[b][n][d]
__device__ float g_qt[BB * DM * NN];   // Q transposed: exp2(-c*u)[b][d][n]

__device__ __forceinline__ float ex2_fast(float x) {
    float y; asm("ex2.approx.f32 %0, %1;" : "=f"(y) : "f"(x)); return y;
}
__device__ __forceinline__ float rcp_fast(float x) {
    float y; asm("rcp.approx.f32 %0, %1;" : "=f"(y) : "f"(x)); return y;
}

// ---------------------------------------------------------------------------
// Kernel A: h = tanh(x @ Wx + bx); P (row-major) / Q (transposed).
// grid = B*N/4 = 256 blocks, 256 threads (thread t owns column d=t)
// ---------------------------------------------------------------------------
__global__ __launch_bounds__(256) void kA(const float* __restrict__ x,
                                          const float* __restrict__ pos,
                                          const float* __restrict__ Wx,
                                          const float* __restrict__ bx,
                                          const float* __restrict__ Wp,
                                          const float* __restrict__ bp) {
    __shared__ float s_x[DIN][4];
    const int t = threadIdx.x;
    const int row0 = blockIdx.x * 4;

    for (int e = t; e < DIN * 4; e += 256) {
        int r = e / DIN, c = e % DIN;
        s_x[c][r] = x[(row0 + r) * DIN + c];
    }
    __syncthreads();

    float bias = bx[t];
    float a0 = bias, a1 = bias, a2 = bias, a3 = bias;
#pragma unroll 8
    for (int k = 0; k < DIN; k++) {
        float wv = Wx[k * DM + t];
        float4 xv = *(const float4*)&s_x[k][0];
        a0 += xv.x * wv;
        a1 += xv.y * wv;
        a2 += xv.z * wv;
        a3 += xv.w * wv;
    }
    g_h[(row0 + 0) * DM + t] = tanhf(a0);
    g_h[(row0 + 1) * DM + t] = tanhf(a1);
    g_h[(row0 + 2) * DM + t] = tanhf(a2);
    g_h[(row0 + 3) * DM + t] = tanhf(a3);

    const int b = row0 / NN;
    const int n0 = row0 % NN;
    const float w0 = Wp[0 * DM + t], w1 = Wp[1 * DM + t];
    const float w2 = Wp[2 * DM + t], w3 = Wp[3 * DM + t];
    const float bpv = bp[t];
#pragma unroll
    for (int r = 0; r < 4; r++) {
        const float* p = pos + (row0 + r) * 4;
        float u = p[0] * w0 + p[1] * w1 + p[2] * w2 + p[3] * w3;
        g_p[(row0 + r) * DM + t] = ex2_fast(C2LOG2E * (u + bpv));   // coalesced
        g_qt[(b * DM + t) * NN + n0 + r] = ex2_fast(-C2LOG2E * u);
    }
}

// ---------------------------------------------------------------------------
// Kernel Score: raw scores -> attn_out.  Block = 2 query rows x 256 j's.
// grid = (B*N/2) * 2 = 1024 blocks, 256 threads. Thread owns one j.
// score_ij = W - 2*sum_d w_d / (1 + P_i[d]*Q_j[d])
// ---------------------------------------------------------------------------
__global__ __launch_bounds__(256) void kScore(const float* __restrict__ w,
                                              float* __restrict__ attn_out) {
    __shared__ float s_pi[DM][2];   // P rows i0, i0+1 : 2KB
    __shared__ float s_wn[DM];      // -2*w : 1KB
    __shared__ float s_W;

    const int t = threadIdx.x;
    const int blk = blockIdx.x;
    const int jt = blk & 1;                 // j-tile
    const int it = blk >> 1;                // row-pair index in [0, B*N/2)
    const int b  = it / (NN / 2);
    const int i0 = (it % (NN / 2)) * 2;
    const int j  = jt * 256 + t;

    if (t < DM) s_wn[t] = -2.0f * w[t];
    if (t < 32) {
        float s = 0.f;
#pragma unroll
        for (int k = 0; k < 8; k++) s += w[t + 32 * k];
#pragma unroll
        for (int o = 16; o; o >>= 1) s += __shfl_xor_sync(0xffffffffu, s, o);
        if (t == 0) s_W = s;
    }
    // coalesced load of two P rows (row-major, 1KB each)
    {
        const float* prow = g_p + (b * NN + i0) * DM;
        for (int e = t; e < 2 * DM; e += 256) {
            int r = e >> 8, d = e & (DM - 1);   // 256 = DM
            s_pi[d][r] = prow[r * DM + d];
        }
    }
    __syncthreads();
    const float W = s_W;

    float a0 = 0.f, a1 = 0.f;
    const float* qp = g_qt + b * DM * NN + j;
    float qbuf[4];
#pragma unroll
    for (int p = 0; p < 4; p++) qbuf[p] = qp[p * NN];

    for (int d0 = 0; d0 < DM; d0 += 4) {
        float qc[4];
#pragma unroll
        for (int p = 0; p < 4; p++) qc[p] = qbuf[p];
        if (d0 + 4 < DM) {
#pragma unroll
            for (int p = 0; p < 4; p++) qbuf[p] = qp[(d0 + 4 + p) * NN];
        }
#pragma unroll
        for (int dd = 0; dd < 4; dd++) {
            const int d = d0 + dd;
            const float2 pi = *(const float2*)&s_pi[d][0];   // broadcast LDS.64
            const float wn = s_wn[d];
            const float qj = qc[dd];
            float de0 = fmaf(pi.x, qj, 1.0f);
            float de1 = fmaf(pi.y, qj, 1.0f);
            float r01 = rcp_fast(de0 * de1);
            float wr = wn * r01;
            a0 += wr * de1;
            a1 += wr * de0;
        }
    }
    float* arow = attn_out + (b * NN + i0) * NN + j;
    arow[0]  = W + a0;
    arow[NN] = W + a1;
}

// ---------------------------------------------------------------------------
// Kernel SoftOut: masked softmax over 4 rows + output GEMM.
// grid = B*N/4 = 256 blocks, 512 threads.
// ---------------------------------------------------------------------------
__global__ __launch_bounds__(512) void kSoftOut(const int* __restrict__ mask,
                                                float* __restrict__ out,
                                                float* __restrict__ attn_out) {
    __shared__ float s_attn[4][NN];   // scores -> probs, 8KB

    const int t = threadIdx.x;
    const int blk = blockIdx.x;
    const int b = blk / (NN / 4);
    const int i0 = (blk % (NN / 4)) * 4;

    // load 4 score rows (coalesced float4)
    {
        const float4* src = (const float4*)(attn_out + (b * NN + i0) * NN);
        float4* dst = (float4*)&s_attn[0][0];
        for (int e = t; e < 4 * NN / 4; e += 512) dst[e] = src[e];
    }
    __syncthreads();

    // masked softmax: warp wid (<4) handles row i0+wid, vectorized int4/float4
    const int wid = t >> 5, lane = t & 31;
    if (wid < 4) {
        const int i = i0 + wid;
        const int4* m4 = (const int4*)(mask + (b * NN + i) * NN);
        float4* s4 = (float4*)&s_attn[wid][0];
        int4 mv[4];
        float4 sv[4];
#pragma unroll
        for (int k = 0; k < 4; k++) {
            mv[k] = m4[lane + 32 * k];
            sv[k] = s4[lane + 32 * k];
        }
        float mx = -INFINITY;
#pragma unroll
        for (int k = 0; k < 4; k++) {
            if (mv[k].x) mx = fmaxf(mx, sv[k].x);
            if (mv[k].y) mx = fmaxf(mx, sv[k].y);
            if (mv[k].z) mx = fmaxf(mx, sv[k].z);
            if (mv[k].w) mx = fmaxf(mx, sv[k].w);
        }
#pragma unroll
        for (int o = 16; o; o >>= 1) mx = fmaxf(mx, __shfl_xor_sync(0xffffffffu, mx, o));
        float sum = 0.f;
#pragma unroll
        for (int k = 0; k < 4; k++) {
            sv[k].x = mv[k].x ? __expf(sv[k].x - mx) : 0.f;
            sv[k].y = mv[k].y ? __expf(sv[k].y - mx) : 0.f;
            sv[k].z = mv[k].z ? __expf(sv[k].z - mx) : 0.f;
            sv[k].w = mv[k].w ? __expf(sv[k].w - mx) : 0.f;
            sum += sv[k].x + sv[k].y + sv[k].z + sv[k].w;
        }
#pragma unroll
        for (int o = 16; o; o >>= 1) sum += __shfl_xor_sync(0xffffffffu, sum, o);
        const float inv = (sum > 0.f) ? 1.f / sum : 0.f;
        float4* arow4 = (float4*)(attn_out + (b * NN + i) * NN);
#pragma unroll
        for (int k = 0; k < 4; k++) {
            sv[k].x *= inv; sv[k].y *= inv; sv[k].z *= inv; sv[k].w *= inv;
            s4[lane + 32 * k] = sv[k];
            arow4[lane + 32 * k] = sv[k];
        }
    }
    __syncthreads();

    // output: thread t -> d = t&255, rows {2*half, 2*half+1}
    const int d = t & (DM - 1);
    const int half = t >> 8;
    float o0 = 0.f, o1 = 0.f;
    const float* hb = g_h + b * NN * DM + d;
    const float4* pA = (const float4*)&s_attn[2 * half][0];
    const float4* pB = (const float4*)&s_attn[2 * half + 1][0];
#pragma unroll 2
    for (int j4 = 0; j4 < NN / 4; j4++) {
        float4 a = pA[j4];  // broadcast LDS.128
        float4 c = pB[j4];
        float h0 = hb[(4 * j4 + 0) * DM];
        float h1 = hb[(4 * j4 + 1) * DM];
        float h2 = hb[(4 * j4 + 2) * DM];
        float h3 = hb[(4 * j4 + 3) * DM];
        o0 += a.x * h0; o0 += a.y * h1; o0 += a.z * h2; o0 += a.w * h3;
        o1 += c.x * h0; o1 += c.y * h1; o1 += c.z * h2; o1 += c.w * h3;
    }
    out[(b * NN + i0 + 2 * half + 0) * DM + d] = o0;
    out[(b * NN + i0 + 2 * half + 1) * DM + d] = o1;
}

// ---------------------------------------------------------------------------
extern "C" void kernel_launch(void* const* d_in, const int* in_sizes, int n_in,
                              void* d_out, int out_size) {
    const float* x    = (const float*)d_in[0];  // [2,512,512]
    const float* pos  = (const float*)d_in[1];  // [2,512,4]
    const int*   mask = (const int*)  d_in[2];  // [2,512,512]
    const float* Wx   = (const float*)d_in[3];  // [512,256]
    const float* bx   = (const float*)d_in[4];  // [256]
    const float* Wp   = (const float*)d_in[5];  // [4,256]
    const float* bp   = (const float*)d_in[6];  // [256]
    const float* w    = (const float*)d_in[7];  // [256]

    float* out      = (float*)d_out;            // [2,512,256]
    float* attn_out = out + BB * NN * DM;       // [2,512,512]

    kA<<<BB * NN / 4, 256>>>(x, pos, Wx, bx, Wp, bp);
    kScore<<<BB * NN, 256>>>(w, attn_out);      // (B*N/2 row-pairs) * 2 j-tiles
    kSoftOut<<<BB * NN / 4, 512>>>(mask, out, attn_out);
}